// round 10
// baseline (speedup 1.0000x reference)
#include <cuda_runtime.h>

// ConceptGaussians: per-domain gather.
//   labels  : [B=2097152, 8] int32 in [0,64)
//   mean    : [8, 64] f32;  log_var : [8, 64] f32
// Output: [ means[B,8] | log_vars[B,8] ] f32.
//
// R8 lesson: perf tracks occupancy (82%->39us, 62%->41.5us, 42%->43.1us).
// R9: grid-stride (4 iters/thread, simple loop, NO prefetch) to amortize the
// table-load prologue 8x vs R5, with __launch_bounds__(512,4) forcing
// regs<=32 so occupancy stays at the 2048-thread/SM cap.

#define TPB   512
#define ITERS 4

__global__ void __launch_bounds__(TPB, 4)
concept_gather_kernel(const int4* __restrict__ lab4,
                      const float* __restrict__ g_mean,
                      const float* __restrict__ g_lv,
                      float4* __restrict__ out_m,
                      float4* __restrict__ out_v,
                      int n)
{
    // Fused (mean, log_var) table: 512 float2 = 4 KiB. One load round (TPB=512).
    __shared__ float2 tab[512];
    if (threadIdx.x < 512)
        tab[threadIdx.x] = make_float2(g_mean[threadIdx.x], g_lv[threadIdx.x]);
    __syncthreads();

    const int stride = gridDim.x * TPB;

    for (int i = blockIdx.x * TPB + threadIdx.x; i < n; i += stride) {
        // 8 labels: two coalesced LDG.128 (streaming — single touch).
        int4 c0 = __ldcs(&lab4[2 * i]);
        int4 c1 = __ldcs(&lab4[2 * i + 1]);

        // Shared-table lookups (domain d at tab[d*64 + idx]).
        float2 t0 = tab[       c0.x];
        float2 t1 = tab[ 64 +  c0.y];
        float2 t2 = tab[128 +  c0.z];
        float2 t3 = tab[192 +  c0.w];
        float2 t4 = tab[256 +  c1.x];
        float2 t5 = tab[320 +  c1.y];
        float2 t6 = tab[384 +  c1.z];
        float2 t7 = tab[448 +  c1.w];

        // Coalesced streaming STG.128 into the two output halves.
        __stcs(&out_m[2 * i],     make_float4(t0.x, t1.x, t2.x, t3.x));
        __stcs(&out_m[2 * i + 1], make_float4(t4.x, t5.x, t6.x, t7.x));
        __stcs(&out_v[2 * i],     make_float4(t0.y, t1.y, t2.y, t3.y));
        __stcs(&out_v[2 * i + 1], make_float4(t4.y, t5.y, t6.y, t7.y));
    }
}

extern "C" void kernel_launch(void* const* d_in, const int* in_sizes, int n_in,
                              void* d_out, int out_size)
{
    const int4*  labels = (const int4*)d_in[0];   // [B,8] int32 as 2x int4
    const float* g_mean = (const float*)d_in[1];  // [8,64]
    const float* g_lv   = (const float*)d_in[2];  // [8,64]

    int n = in_sizes[0] / 8;                      // B samples

    float4* out_m = (float4*)d_out;               // means half
    float4* out_v = out_m + (size_t)n * 2;        // log_var half

    int blocks = (n + TPB * ITERS - 1) / (TPB * ITERS);   // 1024 for B=2M
    concept_gather_kernel<<<blocks, TPB>>>(labels, g_mean, g_lv, out_m, out_v, n);
}

// round 11
// speedup vs baseline: 1.2399x; 1.2399x over previous
#include <cuda_runtime.h>

// ConceptGaussians: per-domain gather.
//   labels  : [B=2097152, 8] int32 in [0,64)
//   mean/log_var : [8, 64] f32
// Output: [ means[B,8] | log_vars[B,8] ] f32.
//
// R10: cp.async (LDGSTS) label staging. MLP lives in SMEM-bound bulk copies
// (24KB/block in flight) instead of registers, so occupancy isn't taxed and
// only one DRAM latency is exposed per block. Thread t copies and consumes
// only its own slots -> no per-stage __syncthreads, wait_group suffices.

#define TPB    256
#define STAGES 3

__device__ __forceinline__ void cp16(void* smem_dst, const void* gmem_src) {
    unsigned s = (unsigned)__cvta_generic_to_shared(smem_dst);
    asm volatile("cp.async.cg.shared.global [%0], [%1], 16;\n"
                 :: "r"(s), "l"(gmem_src) : "memory");
}
__device__ __forceinline__ void cp_commit() {
    asm volatile("cp.async.commit_group;\n" ::: "memory");
}
template <int N>
__device__ __forceinline__ void cp_wait() {
    asm volatile("cp.async.wait_group %0;\n" :: "n"(N) : "memory");
}

__global__ void __launch_bounds__(TPB)
concept_gather_kernel(const int4* __restrict__ lab4,
                      const float* __restrict__ g_mean,
                      const float* __restrict__ g_lv,
                      float4* __restrict__ out_m,
                      float4* __restrict__ out_v,
                      int n)
{
    __shared__ float2 tab[512];               // fused (mean, log_var), 4 KiB
    __shared__ int4 bufA[STAGES][TPB];        // first int4 of each sample
    __shared__ int4 bufB[STAGES][TPB];        // second int4 of each sample

    const int tid  = threadIdx.x;
    const int base = blockIdx.x * (TPB * STAGES) + tid;

    // Kick off ALL label copies first so they fly during table load + barrier.
    #pragma unroll
    for (int s = 0; s < STAGES; s++) {
        int b = base + s * TPB;
        if (b < n) {
            cp16(&bufA[s][tid], &lab4[2 * b]);
            cp16(&bufB[s][tid], &lab4[2 * b + 1]);
        }
        cp_commit();                           // one group per stage (may be empty)
    }

    // Table load (2 rounds of 256) overlaps with the in-flight copies.
    #pragma unroll
    for (int i = tid; i < 512; i += TPB)
        tab[i] = make_float2(g_mean[i], g_lv[i]);
    __syncthreads();

    #pragma unroll
    for (int s = 0; s < STAGES; s++) {
        if      (s == 0) cp_wait<STAGES - 1>();
        else if (s == 1) cp_wait<STAGES - 2>();
        else             cp_wait<0>();

        int b = base + s * TPB;
        if (b >= n) break;

        // Own-slot reads: stride 16B across lanes -> 4-phase floor, no extra conflicts.
        int4 c0 = bufA[s][tid];
        int4 c1 = bufB[s][tid];

        float2 t0 = tab[       c0.x];
        float2 t1 = tab[ 64 +  c0.y];
        float2 t2 = tab[128 +  c0.z];
        float2 t3 = tab[192 +  c0.w];
        float2 t4 = tab[256 +  c1.x];
        float2 t5 = tab[320 +  c1.y];
        float2 t6 = tab[384 +  c1.z];
        float2 t7 = tab[448 +  c1.w];

        __stcs(&out_m[2 * b],     make_float4(t0.x, t1.x, t2.x, t3.x));
        __stcs(&out_m[2 * b + 1], make_float4(t4.x, t5.x, t6.x, t7.x));
        __stcs(&out_v[2 * b],     make_float4(t0.y, t1.y, t2.y, t3.y));
        __stcs(&out_v[2 * b + 1], make_float4(t4.y, t5.y, t6.y, t7.y));
    }
}

extern "C" void kernel_launch(void* const* d_in, const int* in_sizes, int n_in,
                              void* d_out, int out_size)
{
    const int4*  labels = (const int4*)d_in[0];   // [B,8] int32 as 2x int4
    const float* g_mean = (const float*)d_in[1];  // [8,64]
    const float* g_lv   = (const float*)d_in[2];  // [8,64]

    int n = in_sizes[0] / 8;                      // B samples

    float4* out_m = (float4*)d_out;               // means half
    float4* out_v = out_m + (size_t)n * 2;        // log_var half

    int per_block = TPB * STAGES;                 // 768 samples/block
    int blocks = (n + per_block - 1) / per_block; // 2731 for B=2M
    concept_gather_kernel<<<blocks, TPB>>>(labels, g_mean, g_lv, out_m, out_v, n);
}

// round 14
// speedup vs baseline: 1.7007x; 1.3716x over previous
#include <cuda_runtime.h>

// ConceptGaussians: per-domain gather.
//   labels  : [B=2097152, 8] int32 in [0,64)
//   mean/log_var : [8, 64] f32   (4 KiB total -> L1-resident after first touch)
// Output: [ means[B,8] | log_vars[B,8] ] f32.
//
// R11: R5's winning shape (1 sample/thread, 256 TPB) but with the shared-mem
// table REMOVED. Tables are gathered directly via __ldg (32 lines, L1-hit
// after warmup). Kills the per-block prologue (table load + barrier) that
// serialized ~55 rounds/SM, and swaps LDS bank-conflict replays for cheaper
// 2-line divergent LDG replays.

#define TPB 256

__global__ void __launch_bounds__(TPB)
concept_gather_kernel(const int4* __restrict__ lab4,
                      const float* __restrict__ g_mean,
                      const float* __restrict__ g_lv,
                      float4* __restrict__ out_m,
                      float4* __restrict__ out_v,
                      int n)
{
    int b = blockIdx.x * TPB + threadIdx.x;
    if (b >= n) return;

    // 8 labels: two coalesced LDG.128.
    int4 c0 = lab4[2 * b];
    int4 c1 = lab4[2 * b + 1];

    // Direct L1-resident gathers: row d spans 256B = 2 cache lines.
    float m0 = __ldg(g_mean +        c0.x);
    float m1 = __ldg(g_mean +  64 +  c0.y);
    float m2 = __ldg(g_mean + 128 +  c0.z);
    float m3 = __ldg(g_mean + 192 +  c0.w);
    float m4 = __ldg(g_mean + 256 +  c1.x);
    float m5 = __ldg(g_mean + 320 +  c1.y);
    float m6 = __ldg(g_mean + 384 +  c1.z);
    float m7 = __ldg(g_mean + 448 +  c1.w);

    float v0 = __ldg(g_lv   +        c0.x);
    float v1 = __ldg(g_lv   +  64 +  c0.y);
    float v2 = __ldg(g_lv   + 128 +  c0.z);
    float v3 = __ldg(g_lv   + 192 +  c0.w);
    float v4 = __ldg(g_lv   + 256 +  c1.x);
    float v5 = __ldg(g_lv   + 320 +  c1.y);
    float v6 = __ldg(g_lv   + 384 +  c1.z);
    float v7 = __ldg(g_lv   + 448 +  c1.w);

    // Coalesced STG.128 into the two output halves.
    out_m[2 * b]     = make_float4(m0, m1, m2, m3);
    out_m[2 * b + 1] = make_float4(m4, m5, m6, m7);
    out_v[2 * b]     = make_float4(v0, v1, v2, v3);
    out_v[2 * b + 1] = make_float4(v4, v5, v6, v7);
}

extern "C" void kernel_launch(void* const* d_in, const int* in_sizes, int n_in,
                              void* d_out, int out_size)
{
    const int4*  labels = (const int4*)d_in[0];   // [B,8] int32 as 2x int4
    const float* g_mean = (const float*)d_in[1];  // [8,64]
    const float* g_lv   = (const float*)d_in[2];  // [8,64]

    int n = in_sizes[0] / 8;                      // B samples

    float4* out_m = (float4*)d_out;               // means half
    float4* out_v = out_m + (size_t)n * 2;        // log_var half

    int blocks = (n + TPB - 1) / TPB;             // 8192 for B=2M
    concept_gather_kernel<<<blocks, TPB>>>(labels, g_mean, g_lv, out_m, out_v, n);
}